// round 8
// baseline (speedup 1.0000x reference)
#include <cuda_runtime.h>
#include <math.h>

#define Nn    10000
#define FIN   512
#define Hh    8
#define C1v   30
#define F1v   (Hh*C1v)   /* 240 */
#define CHv   64
#define F2v   (Hh*CHv)   /* 512 */
#define NCLSv 64
#define EMAX  160000
#define ETOT  (EMAX+Nn)  /* 170000 */

// ---------------- scratch (device globals; no cudaMalloc allowed) ----------
__device__ float g_h1pre[Nn*F1v];
__device__ float g_acc1 [Nn*F1v];
__device__ float g_h2pre[Nn*F2v];
__device__ float g_att  [Nn*16];      // [n][0:8]=asrc, [8:16]=adst
__device__ float g_amat [F2v*16];     // block-diagonal attention matrix
__device__ int   g_cnt     [Nn];
__device__ int   g_cursor  [Nn];
__device__ int   g_rowstart[Nn+1];
__device__ int   g_esrc[ETOT];
__device__ int   g_edst[ETOT];
__device__ int   g_csrc[ETOT];
__device__ int   g_is64;

// ---------------- helpers --------------------------------------------------
__device__ __forceinline__ void get_edge(const void* ei, int E, int e, int& s, int& d) {
    if (e >= E) { s = d = e - E; return; }
    if (g_is64) {
        const long long* p = (const long long*)ei;
        s = (int)p[e]; d = (int)p[E + e];
    } else {
        const int* p = (const int*)ei;
        s = p[e]; d = p[E + e];
    }
}

__device__ __forceinline__ void atomicMaxFs(float* a, float v) {
    int* ai = (int*)a;
    int old = *ai;
    while (__int_as_float(old) < v) {
        int assumed = old;
        old = atomicCAS(ai, assumed, __float_as_int(v));
        if (old == assumed) break;
    }
}

// detect whether edge_index is int64 or int32 (jax x64 ambiguity)
__global__ void k_detect_idx(const void* ei) {
    if (threadIdx.x == 0 && blockIdx.x == 0) {
        const long long* p = (const long long*)ei;
        int ok = 1;
        for (int i = 0; i < 16; i++) {
            long long v = p[i];
            if (v < 0 || v >= Nn) ok = 0;
        }
        g_is64 = ok;
    }
}

// ---------------- CSR build ------------------------------------------------
__global__ void k_prep(const void* ei, int E) {
    int e = blockIdx.x * blockDim.x + threadIdx.x;
    if (e >= E + Nn) return;
    int s, d; get_edge(ei, E, e, s, d);
    g_esrc[e] = s; g_edst[e] = d;
    atomicAdd(&g_cnt[d], 1);
}

// shuffle-based block-wide scan, 1024 threads, serial over chunks
__global__ void k_scan() {
    __shared__ int wsum[32];
    __shared__ int s_carry;
    int t = threadIdx.x, lane = t & 31, wid = t >> 5;
    if (t == 0) s_carry = 0;
    __syncthreads();
    for (int base = 0; base < Nn; base += 1024) {
        int v = (base + t < Nn) ? g_cnt[base + t] : 0;
        int x = v;
        #pragma unroll
        for (int o = 1; o < 32; o <<= 1) {
            int y = __shfl_up_sync(0xFFFFFFFFu, x, o);
            if (lane >= o) x += y;
        }
        if (lane == 31) wsum[wid] = x;
        __syncthreads();
        if (wid == 0) {
            int w = wsum[lane];
            #pragma unroll
            for (int o = 1; o < 32; o <<= 1) {
                int y = __shfl_up_sync(0xFFFFFFFFu, w, o);
                if (lane >= o) w += y;
            }
            wsum[lane] = w;
        }
        __syncthreads();
        int excl = s_carry + (wid ? wsum[wid - 1] : 0) + x - v;
        if (base + t < Nn) { g_rowstart[base + t] = excl; g_cursor[base + t] = excl; }
        __syncthreads();
        if (t == 0) s_carry += wsum[31];
        __syncthreads();
    }
    if (t == 0) g_rowstart[Nn] = s_carry;
}

__global__ void k_scatter(int tot) {
    int e = blockIdx.x * blockDim.x + threadIdx.x;
    if (e >= tot) return;
    int d = g_edst[e];
    int pos = atomicAdd(&g_cursor[d], 1);
    g_csrc[pos] = g_esrc[e];
}

// ---------------- block-diagonal attention matrix [F,16] -------------------
// amat[(h*C+c)*16 + h]     = a_src[h,c]
// amat[(h*C+c)*16 + 8 + h] = a_dst[h,c]
// (g_amat must be zeroed beforehand by memset)
__global__ void k_build_amat(const float* __restrict__ as,
                             const float* __restrict__ ad, int C) {
    int i = blockIdx.x * blockDim.x + threadIdx.x;
    if (i >= Hh * C) return;
    int h = i / C;
    g_amat[i * 16 + h]     = as[i];
    g_amat[i * 16 + 8 + h] = ad[i];
}

// ---------------- GEMM 64x64 (small-Nc cases) ------------------------------
#define BM 64
#define BN 64
#define BK 16
__global__ __launch_bounds__(256) void k_sgemm(
        const float* __restrict__ A, const float* __restrict__ B,
        float* __restrict__ C, int M, int K, int Nc,
        const float* __restrict__ bias) {
    __shared__ float As[BK][BM];
    __shared__ float Bs[BK][BN];
    int tid = threadIdx.x;
    int tx = tid & 15, ty = tid >> 4;
    int row0 = blockIdx.y * BM, col0 = blockIdx.x * BN;

    float acc[4][4] = {};
    int ar = tid >> 2, ac = (tid & 3) * 4;
    int bk = tid >> 4, bc = (tid & 15) * 4;

    for (int k0 = 0; k0 < K; k0 += BK) {
        float4 av = make_float4(0.f, 0.f, 0.f, 0.f);
        if (row0 + ar < M)
            av = *(const float4*)&A[(long)(row0 + ar) * K + k0 + ac];
        As[ac + 0][ar] = av.x; As[ac + 1][ar] = av.y;
        As[ac + 2][ar] = av.z; As[ac + 3][ar] = av.w;

        float4 bv = make_float4(0.f, 0.f, 0.f, 0.f);
        if (col0 + bc < Nc)
            bv = *(const float4*)&B[(long)(k0 + bk) * Nc + col0 + bc];
        *(float4*)&Bs[bk][bc] = bv;
        __syncthreads();

        #pragma unroll
        for (int kk = 0; kk < BK; kk++) {
            float a[4], b[4];
            #pragma unroll
            for (int i = 0; i < 4; i++) a[i] = As[kk][ty * 4 + i];
            #pragma unroll
            for (int j = 0; j < 4; j++) b[j] = Bs[kk][tx * 4 + j];
            #pragma unroll
            for (int i = 0; i < 4; i++)
                #pragma unroll
                for (int j = 0; j < 4; j++)
                    acc[i][j] += a[i] * b[j];
        }
        __syncthreads();
    }

    #pragma unroll
    for (int i = 0; i < 4; i++) {
        int r = row0 + ty * 4 + i;
        if (r >= M) continue;
        #pragma unroll
        for (int j = 0; j < 4; j++) {
            int c = col0 + tx * 4 + j;
            if (c < Nc)
                C[(long)r * Nc + c] = acc[i][j] + (bias ? bias[c] : 0.f);
        }
    }
}

// ---------------- GEMM 128x128, 8x8 micro-tile, split-4 layout -------------
#define GM 128
#define GN 128
#define GK 16
__global__ __launch_bounds__(256, 2) void k_sgemm128(
        const float* __restrict__ A, const float* __restrict__ B,
        float* __restrict__ C, int M, int K, int Nc) {
    __shared__ float As[GK][GM];
    __shared__ float Bs[GK][GN];
    int tid = threadIdx.x;
    int tx = tid & 15, ty = tid >> 4;
    int row0 = blockIdx.y * GM, col0 = blockIdx.x * GN;

    float acc[8][8] = {};

    for (int k0 = 0; k0 < K; k0 += GK) {
        // A tile: 128 rows x 16 k. Each thread: 2 float4 loads.
        #pragma unroll
        for (int li = 0; li < 2; li++) {
            int i = tid + li * 256;          // float4 index, 0..511
            int r = i >> 2;                  // 0..127
            int kc = (i & 3) * 4;            // 0,4,8,12
            float4 av = make_float4(0.f, 0.f, 0.f, 0.f);
            if (row0 + r < M)
                av = *(const float4*)&A[(long)(row0 + r) * K + k0 + kc];
            As[kc + 0][r] = av.x; As[kc + 1][r] = av.y;
            As[kc + 2][r] = av.z; As[kc + 3][r] = av.w;
        }
        // B tile: 16 k x 128 cols.
        #pragma unroll
        for (int li = 0; li < 2; li++) {
            int i = tid + li * 256;
            int kr = i >> 5;                 // 0..15
            int c = (i & 31) * 4;            // 0..124
            float4 bv = make_float4(0.f, 0.f, 0.f, 0.f);
            if (col0 + c < Nc)
                bv = *(const float4*)&B[(long)(k0 + kr) * Nc + col0 + c];
            *(float4*)&Bs[kr][c] = bv;
        }
        __syncthreads();

        #pragma unroll
        for (int kk = 0; kk < GK; kk++) {
            float a[8], b[8];
            // split-4: rows {ty*4..+3} and {64+ty*4..+3}
            *(float4*)&a[0] = *(const float4*)&As[kk][ty * 4];
            *(float4*)&a[4] = *(const float4*)&As[kk][64 + ty * 4];
            *(float4*)&b[0] = *(const float4*)&Bs[kk][tx * 4];
            *(float4*)&b[4] = *(const float4*)&Bs[kk][64 + tx * 4];
            #pragma unroll
            for (int i = 0; i < 8; i++)
                #pragma unroll
                for (int j = 0; j < 8; j++)
                    acc[i][j] += a[i] * b[j];
        }
        __syncthreads();
    }

    #pragma unroll
    for (int i = 0; i < 8; i++) {
        int r = row0 + ((i < 4) ? (ty * 4 + i) : (64 + ty * 4 + i - 4));
        if (r >= M) continue;
        int c0 = col0 + tx * 4;
        int c1 = col0 + 64 + tx * 4;
        if (c0 + 3 < Nc)
            *(float4*)&C[(long)r * Nc + c0] = make_float4(acc[i][0], acc[i][1], acc[i][2], acc[i][3]);
        if (c1 + 3 < Nc)
            *(float4*)&C[(long)r * Nc + c1] = make_float4(acc[i][4], acc[i][5], acc[i][6], acc[i][7]);
    }
}

// ---------------- fused per-node softmax + aggregate ------------------------
#define CHUNK 64
template<int C, int F, int FPT, int ACT>
__global__ __launch_bounds__(256) void k_node_agg(
        const float* __restrict__ hpre,
        const float* __restrict__ bias,
        float* __restrict__ outp) {
    int node = blockIdx.x;
    int beg = g_rowstart[node], end = g_rowstart[node + 1];
    int deg = end - beg;
    int tid = threadIdx.x;

    __shared__ float s_adst[Hh];
    __shared__ float s_m[Hh], s_sum[Hh];
    __shared__ int   s_src[CHUNK];
    __shared__ float s_w[CHUNK][Hh];

    if (tid < Hh) {
        s_adst[tid] = g_att[node * 16 + 8 + tid];
        s_m[tid] = -1e30f;
        s_sum[tid] = 0.f;
    }
    __syncthreads();

    int pairs = deg * Hh;
    for (int i = tid; i < pairs; i += blockDim.x) {
        int e = i >> 3, h = i & 7;
        int s = g_csrc[beg + e];
        float a = g_att[s * 16 + h] + s_adst[h];
        a = (a > 0.f) ? a : 0.2f * a;
        atomicMaxFs(&s_m[h], a);
    }
    __syncthreads();
    for (int i = tid; i < pairs; i += blockDim.x) {
        int e = i >> 3, h = i & 7;
        int s = g_csrc[beg + e];
        float a = g_att[s * 16 + h] + s_adst[h];
        a = (a > 0.f) ? a : 0.2f * a;
        atomicAdd(&s_sum[h], expf(a - s_m[h]));
    }
    __syncthreads();
    if (tid < Hh) s_sum[tid] = 1.f / (s_sum[tid] + 1e-16f);
    __syncthreads();

    float acc[FPT];
    int   fidx[FPT];
    int   hidx[FPT];
    #pragma unroll
    for (int j = 0; j < FPT; j++) {
        acc[j] = 0.f;
        fidx[j] = tid + j * 256;
        hidx[j] = (fidx[j] < F) ? (fidx[j] / C) : 0;
    }

    for (int c0 = 0; c0 < deg; c0 += CHUNK) {
        int cn = min(CHUNK, deg - c0);
        for (int i = tid; i < cn * Hh; i += blockDim.x) {
            int e = i >> 3, h = i & 7;
            int s = g_csrc[beg + c0 + e];
            if (h == 0) s_src[e] = s;
            float a = g_att[s * 16 + h] + s_adst[h];
            a = (a > 0.f) ? a : 0.2f * a;
            s_w[e][h] = expf(a - s_m[h]) * s_sum[h];
        }
        __syncthreads();
        for (int e = 0; e < cn; e++) {
            const float* hp = hpre + (long)s_src[e] * F;
            #pragma unroll
            for (int j = 0; j < FPT; j++) {
                if (fidx[j] < F)
                    acc[j] += s_w[e][hidx[j]] * hp[fidx[j]];
            }
        }
        __syncthreads();
    }

    #pragma unroll
    for (int j = 0; j < FPT; j++) {
        if (fidx[j] < F) {
            float v = acc[j] + bias[fidx[j]];
            if (ACT) v = (v > 0.f) ? v : expm1f(v);   // ELU alpha=1
            outp[(long)node * F + fidx[j]] = v;
        }
    }
}

static inline int cdiv(long a, int b) { return (int)((a + b - 1) / b); }

extern "C" void kernel_launch(void* const* d_in, const int* in_sizes, int n_in,
                              void* d_out, int out_size) {
    const float* x    = (const float*)d_in[0];
    const void*  ei   = d_in[1];
    const float* W1   = (const float*)d_in[2];
    const float* a1s  = (const float*)d_in[3];
    const float* a1d  = (const float*)d_in[4];
    const float* b1   = (const float*)d_in[5];
    const float* W2   = (const float*)d_in[6];
    const float* a2s  = (const float*)d_in[7];
    const float* a2d  = (const float*)d_in[8];
    const float* b2   = (const float*)d_in[9];
    const float* Wlin = (const float*)d_in[10];
    const float* blin = (const float*)d_in[11];

    int E = in_sizes[1] / 2;
    int tot = E + Nn;
    float* out  = (float*)d_out;              // [N, NCLS]
    float* hout = out + (long)Nn * NCLSv;     // [N, F2]

    float *p_h1pre, *p_acc1, *p_h2pre, *p_att, *p_amat;
    int *p_cnt;
    cudaGetSymbolAddress((void**)&p_h1pre, g_h1pre);
    cudaGetSymbolAddress((void**)&p_acc1,  g_acc1);
    cudaGetSymbolAddress((void**)&p_h2pre, g_h2pre);
    cudaGetSymbolAddress((void**)&p_att,   g_att);
    cudaGetSymbolAddress((void**)&p_amat,  g_amat);
    cudaGetSymbolAddress((void**)&p_cnt,   g_cnt);

    // ---- graph prep (CSR by destination; shared by both layers) ----
    k_detect_idx<<<1, 32>>>(ei);
    cudaMemsetAsync(p_cnt, 0, Nn * sizeof(int));
    k_prep<<<cdiv(tot, 256), 256>>>(ei, E);
    k_scan<<<1, 1024>>>();
    k_scatter<<<cdiv(tot, 256), 256>>>(tot);

    // ---- layer 1 ----
    k_sgemm128<<<dim3(cdiv(F1v, GN), cdiv(Nn, GM)), 256>>>(x, W1, p_h1pre, Nn, FIN, F1v);
    cudaMemsetAsync(p_amat, 0, F1v * 16 * sizeof(float));
    k_build_amat<<<cdiv(Hh * C1v, 256), 256>>>(a1s, a1d, C1v);
    k_sgemm<<<dim3(1, cdiv(Nn, BM)), 256>>>(p_h1pre, p_amat, p_att, Nn, F1v, 16, nullptr);
    k_node_agg<C1v, F1v, 1, 1><<<Nn, 256>>>(p_h1pre, b1, p_acc1);

    // ---- layer 2 ----
    k_sgemm128<<<dim3(cdiv(F2v, GN), cdiv(Nn, GM)), 256>>>(p_acc1, W2, p_h2pre, Nn, F1v, F2v);
    cudaMemsetAsync(p_amat, 0, F2v * 16 * sizeof(float));
    k_build_amat<<<cdiv(Hh * CHv, 256), 256>>>(a2s, a2d, CHv);
    k_sgemm<<<dim3(1, cdiv(Nn, BM)), 256>>>(p_h2pre, p_amat, p_att, Nn, F2v, 16, nullptr);
    k_node_agg<CHv, F2v, 2, 0><<<Nn, 256>>>(p_h2pre, b2, hout);

    // ---- classifier head ----
    k_sgemm<<<dim3(cdiv(NCLSv, BN), cdiv(Nn, BM)), 256>>>(hout, Wlin, out, Nn, F2v, NCLSv, blin);
}